// round 16
// baseline (speedup 1.0000x reference)
#include <cuda_runtime.h>
#include <cuda_fp16.h>
#include <math.h>

// ---------------- problem constants ----------------
#define Bsz   1024
#define Tlen  128
#define Hdim  512
#define NCLS  10

// ---------------- tiling ----------------
#define MT 8            // M tiles (1024/128)
#define NT 16           // N tiles (2048/128) in permuted gate space
#define CH 16           // K chunks (512/32)
#define SLAB8 8192      // 128 rows x 32 cols x 2B, SW64 slab

// ---------------- persistent device state (pre-swizzled) ----------------
__device__ __align__(1024) unsigned char g_Wsw[NT][CH][SLAB8];      // fp16 W, 2MB
__device__ __align__(1024) unsigned char g_hsw[2][MT][CH][SLAB8];   // [parity][mtile][chunk] 2MB (fp16)
__device__ float g_hfin[Bsz * Hdim];
__device__ float g_gxp[3][2048];     // permuted gate-bias table
__device__ unsigned g_rowbar[MT * 32];
__device__ volatile unsigned g_rowsense[MT * 32];

// ---------------- PTX helpers (sm_103 plain — NO tcgen05) ----------------
__device__ __forceinline__ unsigned smem_u32(const void* p) {
    unsigned r;
    asm("{ .reg .u64 t; cvta.to.shared.u64 t, %1; cvt.u32.u64 %0, t; }" : "=r"(r) : "l"(p));
    return r;
}
__device__ __forceinline__ void bulk_g2s(unsigned dst, const void* src, unsigned bytes, unsigned mbar) {
    asm volatile("cp.async.bulk.shared::cluster.global.mbarrier::complete_tx::bytes [%0], [%1], %2, [%3];"
        :: "r"(dst), "l"(src), "r"(bytes), "r"(mbar) : "memory");
}
#define BULK_S2G(g, s, n) asm volatile("cp.async.bulk.global.shared::cta.bulk_group [%0], [%1], %2;" :: "l"(g), "r"(s), "r"(n) : "memory")
#define BULK_COMMIT() asm volatile("cp.async.bulk.commit_group;" ::: "memory")
#define BULK_WAIT0()  asm volatile("cp.async.bulk.wait_group 0;" ::: "memory")
#define MBINIT(a, c)  asm volatile("mbarrier.init.shared.b64 [%0], %1;" :: "r"(a), "r"(c) : "memory")
#define MBEXPECT(a, n) asm volatile("mbarrier.arrive.expect_tx.shared.b64 _, [%0], %1;" :: "r"(a), "r"(n) : "memory")
#define MBARRIVE(a)   asm volatile("mbarrier.arrive.shared.b64 _, [%0];" :: "r"(a) : "memory")
#define FENCE_ASYNC() asm volatile("fence.proxy.async.shared::cta;" ::: "memory")

#define MBWAIT(mbar, parity) do {                                            \
    unsigned _m = (mbar); unsigned _p = (parity); unsigned _done;            \
    asm volatile("{\n\t.reg .pred p;\n\t"                                    \
        "mbarrier.try_wait.parity.acquire.cta.shared::cta.b64 p, [%1], %2;\n\t" \
        "selp.b32 %0, 1, 0, p;\n\t}"                                         \
        : "=r"(_done) : "r"(_m), "r"(_p) : "memory");                        \
    if (!_done) {                                                            \
        asm volatile("{\n\t.reg .pred P1;\n\t"                               \
            "WL_%=:\n\t"                                                     \
            "mbarrier.try_wait.parity.acquire.cta.shared::cta.b64 P1, [%0], %1, 0x989680;\n\t" \
            "@P1 bra.uni WD_%=;\n\t"                                         \
            "bra.uni WL_%=;\n\t"                                             \
            "WD_%=:\n\t}"                                                    \
            :: "r"(_m), "r"(_p) : "memory");                                 \
    }                                                                        \
} while (0)

__device__ __forceinline__ void ldsm4(unsigned* r, unsigned addr) {
    asm volatile("ldmatrix.sync.aligned.m8n8.x4.shared.b16 {%0,%1,%2,%3}, [%4];"
        : "=r"(r[0]), "=r"(r[1]), "=r"(r[2]), "=r"(r[3]) : "r"(addr));
}
__device__ __forceinline__ void mma_f16(float* d, const unsigned* a, unsigned b0, unsigned b1) {
    asm volatile("mma.sync.aligned.m16n8k16.row.col.f32.f16.f16.f32 "
        "{%0,%1,%2,%3}, {%4,%5,%6,%7}, {%8,%9}, {%0,%1,%2,%3};"
        : "+f"(d[0]), "+f"(d[1]), "+f"(d[2]), "+f"(d[3])
        : "r"(a[0]), "r"(a[1]), "r"(a[2]), "r"(a[3]), "r"(b0), "r"(b1));
}

__device__ __forceinline__ unsigned sw64(unsigned o) { return o ^ ((o >> 3) & 0x30); }
// fast activations: tanh.approx.f32 (sm_75+ base ISA)
__device__ __forceinline__ float tanha(float x) {
    float y;
    asm("tanh.approx.f32 %0, %1;" : "=f"(y) : "f"(x));
    return y;
}
__device__ __forceinline__ float siga(float x) {   // sigmoid(x) = 0.5*tanh(x/2)+0.5
    return fmaf(0.5f, tanha(0.5f * x), 0.5f);
}

// ---------------- init ----------------
__global__ void lstm_init(const float* __restrict__ emb,
                          const float* __restrict__ Wx,
                          const float* __restrict__ bias,
                          const float* __restrict__ Wh) {
    int i = blockIdx.x * blockDim.x + threadIdx.x;   // 0 .. 1M-1

    // Wsw: permuted c = hcol*4 + gate; SW64 slabs of 32 k-cols; single fp16
    {
        int c = i >> 9;              // 0..2047
        int k = i & 511;
        int r = (c & 3) * Hdim + (c >> 2);
        float w = Wh[r * Hdim + k];
        int ntile = c >> 7, rl = c & 127, chunk = k >> 5, col = k & 31;
        unsigned byte = (unsigned)((rl >> 3) * 512 + (rl & 7) * 64 + col * 2);
        unsigned so = sw64(byte);
        *(__half*)(g_Wsw[ntile][chunk] + so) = __float2half(w);
    }
    // gx table (permuted)
    if (i < 3 * 2048) {
        int d = i >> 11, c = i & 2047;
        int r = (c & 3) * Hdim + (c >> 2);
        g_gxp[d][c] = bias[r] + Wx[r * 2 + 0] * emb[d * 2 + 0]
                              + Wx[r * 2 + 1] * emb[d * 2 + 1];
    }
    if (i < MT * 32) { g_rowbar[i] = 0u; g_rowsense[i] = 0u; }
}

// ---------------- persistent LSTM ----------------
// smem: [0..64) full[4]+empty[4], [64] wbar, [128..1664) gx,
//       [2048..18432) c, [18432..26624) h stage, [34816..165888) W resident,
//       [165888..231424) 4x16KB A ring (2 chunks per slot)
#define SM_MB     0
#define SM_WBAR   64
#define SM_GX     128
#define SM_C      2048
#define SM_HHI    18432
#define SM_W      34816
#define SM_ABUF   165888
#define ABUFB     16384
#define SMEM_TOTAL (SM_ABUF + 4 * ABUFB)   // 231424

#define NTHR      288   // 8 compute warps + 1 producer warp

__global__ __launch_bounds__(NTHR, 1)
void lstm_persist(const int* __restrict__ x) {
    extern __shared__ char smem[];
    const unsigned sbase = smem_u32(smem);
    const int tid = threadIdx.x;
    const int nt = blockIdx.x, mt = blockIdx.y;
    const int m0 = mt * 128, n0 = nt * 128;

    float* sh_gx = (float*)(smem + SM_GX);
    float* sh_c  = (float*)(smem + SM_C);
    for (int i = tid; i < 384; i += NTHR) {          // strided: 384 > blockDim!
        int d = i >> 7, c = i & 127;
        sh_gx[d * 128 + c] = g_gxp[d][n0 + c];
    }
    for (int i = tid; i < 128 * 32; i += NTHR) sh_c[i] = 0.0f;

    unsigned full[4], empt[4];
#pragma unroll
    for (int i = 0; i < 4; ++i) { full[i] = sbase + SM_MB + i * 8; empt[i] = sbase + SM_MB + 32 + i * 8; }
    const unsigned wbar = sbase + SM_WBAR;
    if (tid == 0) {
#pragma unroll
        for (int i = 0; i < 4; ++i) { MBINIT(full[i], 1); MBINIT(empt[i], 8); }
        MBINIT(wbar, 1);
        FENCE_ASYNC();
    }
    __syncthreads();

    // one-time W residency load (128KB contiguous)
    if (tid == 0) {
        MBEXPECT(wbar, 16 * SLAB8);
        bulk_g2s(sbase + SM_W, g_Wsw[nt], 16 * SLAB8, wbar);
    }

    const int lane = tid & 31, wid = tid >> 5;

    // ---- compute-warp constants (valid for wid < 8): 64(M) x 32(N) tiles ----
    const int wm = wid >> 2, wn = wid & 3;           // wm in {0,1}, wn in {0..3}
    unsigned aRow[4], bRowSw[2];
#pragma unroll
    for (int mi = 0; mi < 4; ++mi) {
        int r = wm * 64 + mi * 16 + (lane & 15);
        aRow[mi] = sw64((unsigned)((r >> 3) * 512 + (r & 7) * 64));
    }
#pragma unroll
    for (int ng = 0; ng < 2; ++ng) {
        int r = wn * 32 + ng * 16 + (lane & 15);
        bRowSw[ng] = sw64((unsigned)((r >> 3) * 512 + (r & 7) * 64));
    }
    const unsigned wbase = sbase + SM_W;
    const unsigned colx = (unsigned)((lane >> 4) * 16);
    const int gsel = lane & 1;
    const int psel = (lane >> 1) & 1;
    const int q = lane >> 2;

    if (wid < 8) MBWAIT(wbar, 0);    // W resident before first B ldsm

    unsigned lsense = 0;             // producer lane 0 only

    for (int t = 0; t < Tlen; ++t) {
        const int par = t & 1, np = par ^ 1;

        if (wid == 8) {
            // -------- producer warp (lane 0 only); t=0: h==0, nothing to load --------
            if (lane == 0 && t >= 1) {
                for (int sl = 0; sl < 8; ++sl) {
                    int buf = sl & 3;
                    unsigned pe = ((sl >> 2) & 1) ^ 1;      // empty-wait parity
                    MBWAIT(empt[buf], pe);
                    unsigned d0 = sbase + SM_ABUF + buf * ABUFB;
                    MBEXPECT(full[buf], ABUFB);
                    bulk_g2s(d0, g_hsw[par][mt][2 * sl], ABUFB, full[buf]);
                }
            }
        } else {
            // -------- x prefetch for this step --------
            int ddv[2][2];
#pragma unroll
            for (int mh = 0; mh < 2; ++mh)
#pragma unroll
                for (int rh = 0; rh < 2; ++rh) {
                    int row = wm * 64 + mh * 32 + gsel * 16 + rh * 8 + q;
                    ddv[mh][rh] = x[(m0 + row) * Tlen + t];
                }

            float acc[4][4][4];
#pragma unroll
            for (int i = 0; i < 4; ++i)
#pragma unroll
                for (int j = 0; j < 4; ++j)
#pragma unroll
                    for (int k = 0; k < 4; ++k) acc[i][j][k] = 0.0f;

            if (t >= 1) {
                // ---- register double-buffered kstep pipeline ----
                // 32 ksteps: kstep j -> slot j>>2, sub (j>>1)&1, kh j&1.
                unsigned Ah[2][4][4], Bf[2][2][4];

                MBWAIT(full[0], 0);
                {
                    unsigned aBase = sbase + SM_ABUF;            // slot0 sub0
                    unsigned bB = wbase;                          // chunk 0
                    unsigned kb = colx;                           // kh 0
#pragma unroll
                    for (int mi = 0; mi < 4; ++mi) ldsm4(Ah[0][mi], aBase + (aRow[mi] ^ kb));
#pragma unroll
                    for (int ng = 0; ng < 2; ++ng) ldsm4(Bf[0][ng], bB + (bRowSw[ng] ^ kb));
                }

#pragma unroll
                for (int it = 0; it < 32; ++it) {
                    const int cur = it & 1;
                    if (it + 1 < 32) {
                        const int nx = it + 1;
                        const int nsl = nx >> 2, nsub = (nx >> 1) & 1, nkh = nx & 1;
                        if ((nx & 3) == 0)
                            MBWAIT(full[nsl & 3], (unsigned)((nsl >> 2) & 1));
                        unsigned aBase = sbase + SM_ABUF + (unsigned)((nsl & 3) * ABUFB + nsub * SLAB8);
                        unsigned bB = wbase + (unsigned)((2 * nsl + nsub) * SLAB8);
                        unsigned kb = (unsigned)(nkh * 32) + colx;
#pragma unroll
                        for (int mi = 0; mi < 4; ++mi) ldsm4(Ah[cur ^ 1][mi], aBase + (aRow[mi] ^ kb));
#pragma unroll
                        for (int ng = 0; ng < 2; ++ng) ldsm4(Bf[cur ^ 1][ng], bB + (bRowSw[ng] ^ kb));
                    }
                    // 16 MMAs on current buffer
#pragma unroll
                    for (int mi = 0; mi < 4; ++mi)
#pragma unroll
                        for (int nj = 0; nj < 4; ++nj) {
                            unsigned b0 = Bf[cur][nj >> 1][nj & 1];
                            unsigned b1 = Bf[cur][nj >> 1][(nj & 1) + 2];
                            mma_f16(acc[mi][nj], Ah[cur][mi], b0, b1);
                        }
                    if ((it & 3) == 3) {
                        __syncwarp();
                        if (lane == 0) MBARRIVE(empt[(it >> 2) & 3]);
                    }
                }
            }

            // -------- fused epilogue (tanh.approx; smem c, smem h stage) --------
            // per 32-row half mh: acc blocks mh*2 + {0,1}; pair exchange per mh
            float oth[2][4][4];
#pragma unroll
            for (int mh = 0; mh < 2; ++mh)
#pragma unroll
                for (int nj = 0; nj < 4; ++nj)
#pragma unroll
                    for (int k = 0; k < 4; ++k) {
                        float sendv = gsel ? acc[mh * 2 + 0][nj][k] : acc[mh * 2 + 1][nj][k];
                        oth[mh][nj][k] = __shfl_xor_sync(0xFFFFFFFFu, sendv, 1);
                    }

#pragma unroll
            for (int mh = 0; mh < 2; ++mh) {
#pragma unroll
                for (int rh = 0; rh < 2; ++rh) {
                    const int row = wm * 64 + mh * 32 + gsel * 16 + rh * 8 + q;
                    const int b = m0 + row;
                    const int dd = ddv[mh][rh];
#pragma unroll
                    for (int nj = 0; nj < 4; ++nj) {
                        float own0 = gsel ? acc[mh * 2 + 1][nj][rh * 2 + 0] : acc[mh * 2 + 0][nj][rh * 2 + 0];
                        float own1 = gsel ? acc[mh * 2 + 1][nj][rh * 2 + 1] : acc[mh * 2 + 0][nj][rh * 2 + 1];
                        float o0 = oth[mh][nj][rh * 2 + 0];
                        float o1 = oth[mh][nj][rh * 2 + 1];
                        float zg = gsel ? o0 : own0;
                        float zi = gsel ? o1 : own1;
                        float zf = gsel ? own0 : o0;
                        float zo = gsel ? own1 : o1;

                        const int hcol = wn * 8 + nj * 2 + psel;
                        const int gxb = dd * 128 + hcol * 4;
                        zg += sh_gx[gxb + 0];
                        zi += sh_gx[gxb + 1];
                        zf += sh_gx[gxb + 2];
                        zo += sh_gx[gxb + 3];

                        const int cidx = row * 32 + hcol;
                        float cold = sh_c[cidx];
                        float cn = tanha(zg) * siga(zi) + cold * siga(zf);
                        float hn = tanha(cn) * siga(zo);
                        sh_c[cidx] = cn;

                        unsigned so = sw64((unsigned)((row >> 3) * 512 + (row & 7) * 64 + hcol * 2));
                        *(__half*)(smem + SM_HHI + so) = __float2half(hn);

                        if (t == Tlen - 1)
                            g_hfin[b * Hdim + nt * 32 + hcol] = hn;
                    }
                }
            }
        }

        // stage complete block-wide; producer publishes + row barrier while
        // compute warps run ahead into step t+1.
        __syncthreads();
        if (wid == 8 && lane == 0) {
            FENCE_ASYNC();
            BULK_S2G((void*)g_hsw[np][mt][nt], sbase + SM_HHI, SLAB8);
            BULK_COMMIT();
            BULK_WAIT0();
            __threadfence();
            // row-scoped barrier: only the 16 CTAs sharing mt exchange A slabs
            unsigned s = lsense ^ 1u;
            if (atomicAdd(&g_rowbar[mt * 32], 1u) == (unsigned)(NT - 1)) {
                g_rowbar[mt * 32] = 0u;
                __threadfence();
                g_rowsense[mt * 32] = s;
            } else {
                while (g_rowsense[mt * 32] != s) { }
            }
            lsense = s;
        }
    }
}

// ---------------- head: p = h @ Wp + bp; log_softmax ----------------
__global__ void lstm_head(const float* __restrict__ Wp,
                          const float* __restrict__ bp,
                          float* __restrict__ out) {
    int warp = threadIdx.x >> 5;
    int lane = threadIdx.x & 31;
    int row = blockIdx.x * 8 + warp;
    if (row >= Bsz) return;

    const float* __restrict__ h = &g_hfin[row * Hdim];
    float acc[NCLS];
#pragma unroll
    for (int n = 0; n < NCLS; ++n) acc[n] = 0.0f;
    for (int k = lane; k < Hdim; k += 32) {
        float hv = h[k];
#pragma unroll
        for (int n = 0; n < NCLS; ++n) acc[n] += hv * Wp[k * NCLS + n];
    }
#pragma unroll
    for (int off = 16; off > 0; off >>= 1)
#pragma unroll
        for (int n = 0; n < NCLS; ++n)
            acc[n] += __shfl_xor_sync(0xFFFFFFFFu, acc[n], off);

    if (lane == 0) {
        float p[NCLS], m = -1e30f;
#pragma unroll
        for (int n = 0; n < NCLS; ++n) { p[n] = acc[n] + bp[n]; m = fmaxf(m, p[n]); }
        float ssum = 0.0f;
#pragma unroll
        for (int n = 0; n < NCLS; ++n) ssum += expf(p[n] - m);
        float lse = m + logf(ssum);
#pragma unroll
        for (int n = 0; n < NCLS; ++n) out[row * NCLS + n] = p[n] - lse;
    }
}

extern "C" void kernel_launch(void* const* d_in, const int* in_sizes, int n_in,
                              void* d_out, int out_size) {
    const int*   x   = (const int*)  d_in[0];
    const float* emb = (const float*)d_in[1];
    const float* Wx  = (const float*)d_in[2];
    const float* Wh  = (const float*)d_in[3];
    const float* b   = (const float*)d_in[4];
    const float* Wp  = (const float*)d_in[5];
    const float* bp  = (const float*)d_in[6];
    float* out = (float*)d_out;

    cudaFuncSetAttribute(lstm_persist, cudaFuncAttributeMaxDynamicSharedMemorySize, SMEM_TOTAL);

    lstm_init<<<4096, 256>>>(emb, Wx, b, Wh);

    dim3 grid(NT, MT);   // 16 x 8 = 128 CTAs, 1 per SM -> co-resident
    lstm_persist<<<grid, NTHR, SMEM_TOTAL>>>(x);

    lstm_head<<<Bsz / 8, 256>>>(Wp, bp, out);
}

// round 17
// speedup vs baseline: 1.0316x; 1.0316x over previous
#include <cuda_runtime.h>
#include <cuda_fp16.h>
#include <math.h>

// ---------------- problem constants ----------------
#define Bsz   1024
#define Tlen  128
#define Hdim  512
#define NCLS  10

// ---------------- tiling ----------------
#define MT 8            // M tiles (1024/128)
#define NT 16           // N tiles (2048/128) in permuted gate space
#define CH 16           // K chunks (512/32)
#define SLAB8 8192      // 128 rows x 32 cols x 2B, SW64 slab

// ---------------- persistent device state (pre-swizzled) ----------------
__device__ __align__(1024) unsigned char g_Wsw[NT][CH][SLAB8];      // fp16 W, 2MB
__device__ __align__(1024) unsigned char g_hsw[2][MT][CH][SLAB8];   // [parity][mtile][chunk] 2MB (fp16)
__device__ float g_hfin[Bsz * Hdim];
__device__ float g_gxp[3][2048];     // permuted gate-bias table
__device__ unsigned g_rowbar[MT * 32];
__device__ volatile unsigned g_rowsense[MT * 32];

// ---------------- PTX helpers (sm_103 plain — NO tcgen05) ----------------
__device__ __forceinline__ unsigned smem_u32(const void* p) {
    unsigned r;
    asm("{ .reg .u64 t; cvta.to.shared.u64 t, %1; cvt.u32.u64 %0, t; }" : "=r"(r) : "l"(p));
    return r;
}
__device__ __forceinline__ void bulk_g2s(unsigned dst, const void* src, unsigned bytes, unsigned mbar) {
    asm volatile("cp.async.bulk.shared::cluster.global.mbarrier::complete_tx::bytes [%0], [%1], %2, [%3];"
        :: "r"(dst), "l"(src), "r"(bytes), "r"(mbar) : "memory");
}
#define BULK_S2G(g, s, n) asm volatile("cp.async.bulk.global.shared::cta.bulk_group [%0], [%1], %2;" :: "l"(g), "r"(s), "r"(n) : "memory")
#define BULK_COMMIT() asm volatile("cp.async.bulk.commit_group;" ::: "memory")
#define BULK_WAIT0()  asm volatile("cp.async.bulk.wait_group 0;" ::: "memory")
#define MBINIT(a, c)  asm volatile("mbarrier.init.shared.b64 [%0], %1;" :: "r"(a), "r"(c) : "memory")
#define MBEXPECT(a, n) asm volatile("mbarrier.arrive.expect_tx.shared.b64 _, [%0], %1;" :: "r"(a), "r"(n) : "memory")
#define MBARRIVE(a)   asm volatile("mbarrier.arrive.shared.b64 _, [%0];" :: "r"(a) : "memory")
#define FENCE_ASYNC() asm volatile("fence.proxy.async.shared::cta;" ::: "memory")

#define MBWAIT(mbar, parity) do {                                            \
    unsigned _m = (mbar); unsigned _p = (parity); unsigned _done;            \
    asm volatile("{\n\t.reg .pred p;\n\t"                                    \
        "mbarrier.try_wait.parity.acquire.cta.shared::cta.b64 p, [%1], %2;\n\t" \
        "selp.b32 %0, 1, 0, p;\n\t}"                                         \
        : "=r"(_done) : "r"(_m), "r"(_p) : "memory");                        \
    if (!_done) {                                                            \
        asm volatile("{\n\t.reg .pred P1;\n\t"                               \
            "WL_%=:\n\t"                                                     \
            "mbarrier.try_wait.parity.acquire.cta.shared::cta.b64 P1, [%0], %1, 0x989680;\n\t" \
            "@P1 bra.uni WD_%=;\n\t"                                         \
            "bra.uni WL_%=;\n\t"                                             \
            "WD_%=:\n\t}"                                                    \
            :: "r"(_m), "r"(_p) : "memory");                                 \
    }                                                                        \
} while (0)

__device__ __forceinline__ void ldsm4(unsigned* r, unsigned addr) {
    asm volatile("ldmatrix.sync.aligned.m8n8.x4.shared.b16 {%0,%1,%2,%3}, [%4];"
        : "=r"(r[0]), "=r"(r[1]), "=r"(r[2]), "=r"(r[3]) : "r"(addr));
}
__device__ __forceinline__ void mma_f16(float* d, const unsigned* a, unsigned b0, unsigned b1) {
    asm volatile("mma.sync.aligned.m16n8k16.row.col.f32.f16.f16.f32 "
        "{%0,%1,%2,%3}, {%4,%5,%6,%7}, {%8,%9}, {%0,%1,%2,%3};"
        : "+f"(d[0]), "+f"(d[1]), "+f"(d[2]), "+f"(d[3])
        : "r"(a[0]), "r"(a[1]), "r"(a[2]), "r"(a[3]), "r"(b0), "r"(b1));
}

__device__ __forceinline__ unsigned sw64(unsigned o) { return o ^ ((o >> 3) & 0x30); }
// fast activations: tanh.approx.f32 (sm_75+ base ISA)
__device__ __forceinline__ float tanha(float x) {
    float y;
    asm("tanh.approx.f32 %0, %1;" : "=f"(y) : "f"(x));
    return y;
}
__device__ __forceinline__ float siga(float x) {   // sigmoid(x) = 0.5*tanh(x/2)+0.5
    return fmaf(0.5f, tanha(0.5f * x), 0.5f);
}

// ---------------- init ----------------
__global__ void lstm_init(const float* __restrict__ emb,
                          const float* __restrict__ Wx,
                          const float* __restrict__ bias,
                          const float* __restrict__ Wh) {
    int i = blockIdx.x * blockDim.x + threadIdx.x;   // 0 .. 1M-1

    // Wsw: permuted c = hcol*4 + gate; SW64 slabs of 32 k-cols; single fp16
    {
        int c = i >> 9;              // 0..2047
        int k = i & 511;
        int r = (c & 3) * Hdim + (c >> 2);
        float w = Wh[r * Hdim + k];
        int ntile = c >> 7, rl = c & 127, chunk = k >> 5, col = k & 31;
        unsigned byte = (unsigned)((rl >> 3) * 512 + (rl & 7) * 64 + col * 2);
        unsigned so = sw64(byte);
        *(__half*)(g_Wsw[ntile][chunk] + so) = __float2half(w);
    }
    // gx table (permuted)
    if (i < 3 * 2048) {
        int d = i >> 11, c = i & 2047;
        int r = (c & 3) * Hdim + (c >> 2);
        g_gxp[d][c] = bias[r] + Wx[r * 2 + 0] * emb[d * 2 + 0]
                              + Wx[r * 2 + 1] * emb[d * 2 + 1];
    }
    if (i < MT * 32) { g_rowbar[i] = 0u; g_rowsense[i] = 0u; }
}

// ---------------- persistent LSTM ----------------
// smem: [0..64) full[4]+empty[4], [64] wbar, [128..1664) gx,
//       [2048..18432) c, [18432..26624) h stage, [34816..165888) W resident,
//       [165888..231424) 4x16KB A ring (2 chunks per slot)
#define SM_MB     0
#define SM_WBAR   64
#define SM_GX     128
#define SM_C      2048
#define SM_HHI    18432
#define SM_W      34816
#define SM_ABUF   165888
#define ABUFB     16384
#define SMEM_TOTAL (SM_ABUF + 4 * ABUFB)   // 231424

__global__ __launch_bounds__(544, 1)
void lstm_persist(const int* __restrict__ x) {
    extern __shared__ char smem[];
    const unsigned sbase = smem_u32(smem);
    const int tid = threadIdx.x;
    const int nt = blockIdx.x, mt = blockIdx.y;
    const int m0 = mt * 128, n0 = nt * 128;

    float* sh_gx = (float*)(smem + SM_GX);
    float* sh_c  = (float*)(smem + SM_C);
    if (tid < 384) {
        int d = tid >> 7, c = tid & 127;
        sh_gx[d * 128 + c] = g_gxp[d][n0 + c];
    }
    for (int i = tid; i < 128 * 32; i += 544) sh_c[i] = 0.0f;

    unsigned full[4], empt[4];
#pragma unroll
    for (int i = 0; i < 4; ++i) { full[i] = sbase + SM_MB + i * 8; empt[i] = sbase + SM_MB + 32 + i * 8; }
    const unsigned wbar = sbase + SM_WBAR;
    if (tid == 0) {
#pragma unroll
        for (int i = 0; i < 4; ++i) { MBINIT(full[i], 1); MBINIT(empt[i], 16); }
        MBINIT(wbar, 1);
        FENCE_ASYNC();
    }
    __syncthreads();

    // one-time W residency load (128KB contiguous)
    if (tid == 0) {
        MBEXPECT(wbar, 16 * SLAB8);
        bulk_g2s(sbase + SM_W, g_Wsw[nt], 16 * SLAB8, wbar);
    }

    const int lane = tid & 31, wid = tid >> 5;

    // ---- compute-warp constants (valid for wid < 16) ----
    const int wm = wid >> 2, wn = wid & 3;
    unsigned aRow[2], bRowSw[2];
#pragma unroll
    for (int mi = 0; mi < 2; ++mi) {
        int r = wm * 32 + mi * 16 + (lane & 15);
        aRow[mi] = sw64((unsigned)((r >> 3) * 512 + (r & 7) * 64));
    }
#pragma unroll
    for (int ng = 0; ng < 2; ++ng) {
        int r = wn * 32 + ng * 16 + (lane & 15);
        bRowSw[ng] = sw64((unsigned)((r >> 3) * 512 + (r & 7) * 64));
    }
    const unsigned wbase = sbase + SM_W;
    const unsigned colx = (unsigned)((lane >> 4) * 16);
    const int gsel = lane & 1;
    const int psel = (lane >> 1) & 1;
    const int q = lane >> 2;

    if (wid < 16) MBWAIT(wbar, 0);   // W resident before first B ldsm

    unsigned lsense = 0;             // producer lane 0 only

    for (int t = 0; t < Tlen; ++t) {
        const int par = t & 1, np = par ^ 1;

        if (wid == 16) {
            // -------- producer warp (lane 0 only); t=0: h==0, nothing to load --------
            if (lane == 0 && t >= 1) {
                for (int sl = 0; sl < 8; ++sl) {
                    int buf = sl & 3;
                    unsigned pe = ((sl >> 2) & 1) ^ 1;      // empty-wait parity
                    MBWAIT(empt[buf], pe);
                    unsigned d0 = sbase + SM_ABUF + buf * ABUFB;
                    MBEXPECT(full[buf], ABUFB);
                    bulk_g2s(d0, g_hsw[par][mt][2 * sl], ABUFB, full[buf]);
                }
            }
        } else {
            // -------- x prefetch for this step --------
            int ddv[2];
#pragma unroll
            for (int rh = 0; rh < 2; ++rh) {
                int row = wm * 32 + gsel * 16 + rh * 8 + q;
                ddv[rh] = x[(m0 + row) * Tlen + t];
            }

            float acc[2][4][4];
#pragma unroll
            for (int i = 0; i < 2; ++i)
#pragma unroll
                for (int j = 0; j < 4; ++j)
#pragma unroll
                    for (int k = 0; k < 4; ++k) acc[i][j][k] = 0.0f;

            if (t >= 1) {
                // ---- register double-buffered kstep pipeline ----
                // 32 ksteps: kstep j -> slot j>>2, sub (j>>1)&1, kh j&1.
                unsigned Ah[2][2][4], Bf[2][2][4];

                MBWAIT(full[0], 0);
                {
                    unsigned aBase = sbase + SM_ABUF;            // slot0 sub0
                    unsigned bB = wbase;                          // chunk 0
                    unsigned kb = colx;                           // kh 0
#pragma unroll
                    for (int mi = 0; mi < 2; ++mi) ldsm4(Ah[0][mi], aBase + (aRow[mi] ^ kb));
#pragma unroll
                    for (int ng = 0; ng < 2; ++ng) ldsm4(Bf[0][ng], bB + (bRowSw[ng] ^ kb));
                }

#pragma unroll
                for (int it = 0; it < 32; ++it) {
                    const int cur = it & 1;
                    if (it + 1 < 32) {
                        const int nx = it + 1;
                        const int nsl = nx >> 2, nsub = (nx >> 1) & 1, nkh = nx & 1;
                        if ((nx & 3) == 0)
                            MBWAIT(full[nsl & 3], (unsigned)((nsl >> 2) & 1));
                        unsigned aBase = sbase + SM_ABUF + (unsigned)((nsl & 3) * ABUFB + nsub * SLAB8);
                        unsigned bB = wbase + (unsigned)((2 * nsl + nsub) * SLAB8);
                        unsigned kb = (unsigned)(nkh * 32) + colx;
#pragma unroll
                        for (int mi = 0; mi < 2; ++mi) ldsm4(Ah[cur ^ 1][mi], aBase + (aRow[mi] ^ kb));
#pragma unroll
                        for (int ng = 0; ng < 2; ++ng) ldsm4(Bf[cur ^ 1][ng], bB + (bRowSw[ng] ^ kb));
                    }
#pragma unroll
                    for (int mi = 0; mi < 2; ++mi)
#pragma unroll
                        for (int nj = 0; nj < 4; ++nj) {
                            unsigned b0 = Bf[cur][nj >> 1][nj & 1];
                            unsigned b1 = Bf[cur][nj >> 1][(nj & 1) + 2];
                            mma_f16(acc[mi][nj], Ah[cur][mi], b0, b1);
                        }
                    if ((it & 3) == 3) {
                        __syncwarp();
                        if (lane == 0) MBARRIVE(empt[(it >> 2) & 3]);
                    }
                }
            }

            // -------- fused epilogue (tanh.approx; float4 gx; smem c, h stage) --------
            float oth[4][4];
#pragma unroll
            for (int nj = 0; nj < 4; ++nj)
#pragma unroll
                for (int k = 0; k < 4; ++k) {
                    float sendv = gsel ? acc[0][nj][k] : acc[1][nj][k];
                    oth[nj][k] = __shfl_xor_sync(0xFFFFFFFFu, sendv, 1);
                }

#pragma unroll
            for (int rh = 0; rh < 2; ++rh) {
                const int row = wm * 32 + gsel * 16 + rh * 8 + q;
                const int b = m0 + row;
                const int dd = ddv[rh];
#pragma unroll
                for (int nj = 0; nj < 4; ++nj) {
                    float own0 = gsel ? acc[1][nj][rh * 2 + 0] : acc[0][nj][rh * 2 + 0];
                    float own1 = gsel ? acc[1][nj][rh * 2 + 1] : acc[0][nj][rh * 2 + 1];
                    float o0 = oth[nj][rh * 2 + 0];
                    float o1 = oth[nj][rh * 2 + 1];
                    float zg = gsel ? o0 : own0;
                    float zi = gsel ? o1 : own1;
                    float zf = gsel ? own0 : o0;
                    float zo = gsel ? own1 : o1;

                    const int hcol = wn * 8 + nj * 2 + psel;
                    // gate biases: one 16B-aligned float4 LDS (gxb = dd*128 + hcol*4)
                    float4 gx4 = *(const float4*)&sh_gx[dd * 128 + hcol * 4];
                    zg += gx4.x;
                    zi += gx4.y;
                    zf += gx4.z;
                    zo += gx4.w;

                    const int cidx = row * 32 + hcol;
                    float cold = sh_c[cidx];
                    float cn = tanha(zg) * siga(zi) + cold * siga(zf);
                    float hn = tanha(cn) * siga(zo);
                    sh_c[cidx] = cn;

                    unsigned so = sw64((unsigned)((row >> 3) * 512 + (row & 7) * 64 + hcol * 2));
                    *(__half*)(smem + SM_HHI + so) = __float2half(hn);

                    if (t == Tlen - 1)
                        g_hfin[b * Hdim + nt * 32 + hcol] = hn;
                }
            }
        }

        // stage complete block-wide; producer publishes + row barrier while
        // compute warps run ahead into step t+1. Final step: nothing consumes
        // the h slabs -> skip publish and barrier entirely.
        __syncthreads();
        if (t < Tlen - 1 && wid == 16 && lane == 0) {
            FENCE_ASYNC();
            BULK_S2G((void*)g_hsw[np][mt][nt], sbase + SM_HHI, SLAB8);
            BULK_COMMIT();
            BULK_WAIT0();
            __threadfence();
            // row-scoped barrier: only the 16 CTAs sharing mt exchange A slabs
            unsigned s = lsense ^ 1u;
            if (atomicAdd(&g_rowbar[mt * 32], 1u) == (unsigned)(NT - 1)) {
                g_rowbar[mt * 32] = 0u;
                __threadfence();
                g_rowsense[mt * 32] = s;
            } else {
                while (g_rowsense[mt * 32] != s) { }
            }
            lsense = s;
        }
    }
}

// ---------------- head: p = h @ Wp + bp; log_softmax ----------------
__global__ void lstm_head(const float* __restrict__ Wp,
                          const float* __restrict__ bp,
                          float* __restrict__ out) {
    int warp = threadIdx.x >> 5;
    int lane = threadIdx.x & 31;
    int row = blockIdx.x * 8 + warp;
    if (row >= Bsz) return;

    const float* __restrict__ h = &g_hfin[row * Hdim];
    float acc[NCLS];
#pragma unroll
    for (int n = 0; n < NCLS; ++n) acc[n] = 0.0f;
    for (int k = lane; k < Hdim; k += 32) {
        float hv = h[k];
#pragma unroll
        for (int n = 0; n < NCLS; ++n) acc[n] += hv * Wp[k * NCLS + n];
    }
#pragma unroll
    for (int off = 16; off > 0; off >>= 1)
#pragma unroll
        for (int n = 0; n < NCLS; ++n)
            acc[n] += __shfl_xor_sync(0xFFFFFFFFu, acc[n], off);

    if (lane == 0) {
        float p[NCLS], m = -1e30f;
#pragma unroll
        for (int n = 0; n < NCLS; ++n) { p[n] = acc[n] + bp[n]; m = fmaxf(m, p[n]); }
        float ssum = 0.0f;
#pragma unroll
        for (int n = 0; n < NCLS; ++n) ssum += expf(p[n] - m);
        float lse = m + logf(ssum);
#pragma unroll
        for (int n = 0; n < NCLS; ++n) out[row * NCLS + n] = p[n] - lse;
    }
}

extern "C" void kernel_launch(void* const* d_in, const int* in_sizes, int n_in,
                              void* d_out, int out_size) {
    const int*   x   = (const int*)  d_in[0];
    const float* emb = (const float*)d_in[1];
    const float* Wx  = (const float*)d_in[2];
    const float* Wh  = (const float*)d_in[3];
    const float* b   = (const float*)d_in[4];
    const float* Wp  = (const float*)d_in[5];
    const float* bp  = (const float*)d_in[6];
    float* out = (float*)d_out;

    cudaFuncSetAttribute(lstm_persist, cudaFuncAttributeMaxDynamicSharedMemorySize, SMEM_TOTAL);

    lstm_init<<<4096, 256>>>(emb, Wx, b, Wh);

    dim3 grid(NT, MT);   // 16 x 8 = 128 CTAs, 1 per SM -> co-resident
    lstm_persist<<<grid, 544, SMEM_TOTAL>>>(x);

    lstm_head<<<Bsz / 8, 256>>>(Wp, bp, out);
}